// round 11
// baseline (speedup 1.0000x reference)
#include <cuda_runtime.h>
#include <cuda_fp16.h>
#include <cstdint>

// ---------------- problem dims ----------------
#define B_DIM 4096
#define SF    256
#define FC    512
#define ADIM  16
#define NSLOT 17            // 16 advantage slots + 1 state slot

// ---------------- GEMM tiles ------------------
#define BM 128
#define BN 128
#define BK 32
#define NT 256              // 8 warps: 2 (M) x 4 (N), warp tile 64x32

#define SROW   40                        // smem row stride in halves = 80 bytes
#define PLANE  (128 * SROW * 2)          // 10240 B per plane (128 rows)
#define SM_A   0
#define SM_B   PLANE
#define STAGE_BYTES (2 * PLANE)          // 20480
#define STAGES 4
#define SM_BIAS (STAGES * STAGE_BYTES)   // 81920
#define SMEM_TOTAL (SM_BIAS + BN * 4)    // 82432

// ---------------- device scratch (no cudaMalloc allowed) ----
__device__ __half g_x[(size_t)B_DIM * SF];                    // fp16 activations
__device__ __half g_H1[(size_t)NSLOT * B_DIM * FC];
__device__ __half g_H2[(size_t)NSLOT * B_DIM * FC];
// transposed fp16 weights: [slot][N][K]
__device__ __half g_W1[(size_t)NSLOT * FC * SF];
__device__ __half g_W2[(size_t)NSLOT * FC * FC];
__device__ __half g_W3[(size_t)NSLOT * SF * FC];
__device__ float g_S[(size_t)B_DIM * SF];

// ---------------- helpers ----------------
__device__ __forceinline__ uint32_t smem_u32(const void* p) {
    uint32_t a;
    asm("{ .reg .u64 t; cvta.to.shared.u64 t, %1; cvt.u32.u64 %0, t; }" : "=r"(a) : "l"(p));
    return a;
}
__device__ __forceinline__ void ldm_x4(uint32_t* r, uint32_t addr) {
    asm volatile("ldmatrix.sync.aligned.m8n8.x4.shared.b16 {%0,%1,%2,%3}, [%4];"
                 : "=r"(r[0]), "=r"(r[1]), "=r"(r[2]), "=r"(r[3]) : "r"(addr));
}
__device__ __forceinline__ void mma16816(float* d, const uint32_t* a, const uint32_t* b) {
    asm volatile("mma.sync.aligned.m16n8k16.row.col.f32.f16.f16.f32 "
                 "{%0,%1,%2,%3}, {%4,%5,%6,%7}, {%8,%9}, {%0,%1,%2,%3};"
                 : "+f"(d[0]), "+f"(d[1]), "+f"(d[2]), "+f"(d[3])
                 : "r"(a[0]), "r"(a[1]), "r"(a[2]), "r"(a[3]), "r"(b[0]), "r"(b[1]));
}
__device__ __forceinline__ void cpasync16(uint32_t dst, const void* src) {
    asm volatile("cp.async.cg.shared.global [%0], [%1], 16;" :: "r"(dst), "l"(src));
}
#define CP_COMMIT() asm volatile("cp.async.commit_group;" ::: "memory")
#define CP_WAIT2()  asm volatile("cp.async.wait_group 2;" ::: "memory")

// ======================================================================
// Prologue 1: round fp32 -> fp16 (activations input)
// ======================================================================
__global__ void round_kernel(const float* __restrict__ src,
                             __half* __restrict__ dst, int n4) {
    int i = blockIdx.x * blockDim.x + threadIdx.x;
    if (i >= n4) return;
    float4 v = reinterpret_cast<const float4*>(src)[i];
    __half2 h0 = __floats2half2_rn(v.x, v.y);
    __half2 h1 = __floats2half2_rn(v.z, v.w);
    reinterpret_cast<__half2*>(dst)[2 * i] = h0;
    reinterpret_cast<__half2*>(dst)[2 * i + 1] = h1;
}

// ======================================================================
// Prologue 2: transpose [K,N] fp32 -> [N,K] fp16; slot 16 = alt src
// ======================================================================
__global__ void transpose_round(const float* __restrict__ src_main, size_t sstride,
                                const float* __restrict__ src_alt,
                                __half* __restrict__ dst, int K, int N) {
    __shared__ float tile[32][33];
    const int a = blockIdx.z;
    const float* src = (a < ADIM) ? (src_main + (size_t)a * sstride) : src_alt;
    const int k0 = blockIdx.x * 32, n0 = blockIdx.y * 32;
    const int tx = threadIdx.x, ty = threadIdx.y;   // 32 x 8
#pragma unroll
    for (int r = 0; r < 32; r += 8)
        tile[ty + r][tx] = src[(size_t)(k0 + ty + r) * N + n0 + tx];
    __syncthreads();
    const size_t obase = ((size_t)a * N + n0) * K + k0;
#pragma unroll
    for (int r = 0; r < 32; r += 8)
        dst[obase + (size_t)(ty + r) * K + tx] = __float2half_rn(tile[tx][ty + r]);
}

// ======================================================================
// Batched GEMM: O = [relu](A @ W^T + bias), pure fp16 operands, fp32 accum.
// A: fp16 [M,K]; W: [NSLOT][N,K] fp16.
// outmode 0: write fp16 plane. outmode 1: fp32 (main/alt).
// ======================================================================
__global__ void __launch_bounds__(NT, 1)
gemm_mma(const __half* __restrict__ Abase, size_t sAz,
         const __half* __restrict__ Wbase, size_t sWz,
         const float* __restrict__ bmain, size_t sbz, const float* __restrict__ balt,
         __half* __restrict__ Oh, size_t sOz,
         float* __restrict__ Ofm, size_t sOfz, int ldo_f,
         float* __restrict__ Ofa, int ldo_a,
         int K, int ldn, int relu_f, int outmode)
{
    extern __shared__ __align__(16) char smem[];
    const uint32_t smem_base = smem_u32(smem);
    const int tid  = threadIdx.x;
    const int wid  = tid >> 5;
    const int lane = tid & 31;
    const int wm   = wid >> 2;
    const int wn   = wid & 3;
    const int a   = blockIdx.z;
    const int m0  = blockIdx.x * BM;
    const int n0  = blockIdx.y * BN;

    const __half* As = Abase + (size_t)a * sAz;
    const __half* Ws = Wbase + (size_t)a * sWz;
    const float* bsel = (a < ADIM) ? (bmain + (size_t)a * sbz) : balt;

    float* sBias = (float*)(smem + SM_BIAS);
    if (tid < BN) sBias[tid] = bsel[n0 + tid];

    const size_t Ksz = (size_t)K;

    // cp.async tasks: 512 16B-chunks per plane -> 2/thread each for A and B.
    auto prefetch = [&](int stage, int c) {
        const uint32_t sb = smem_base + stage * STAGE_BYTES;
        const size_t kA = (size_t)c * BK;
#pragma unroll
        for (int r = 0; r < 2; ++r) {
            int t = tid + r * NT;
            int row = t >> 2, ch = t & 3;
            size_t offA = (size_t)(m0 + row) * Ksz + kA + ch * 8;
            cpasync16(sb + SM_A + row * 80 + ch * 16, As + offA);
            size_t offB = (size_t)(n0 + row) * Ksz + kA + ch * 8;
            cpasync16(sb + SM_B + row * 80 + ch * 16, Ws + offB);
        }
    };

    float acc[4][4][4];
#pragma unroll
    for (int i = 0; i < 4; ++i)
#pragma unroll
        for (int j = 0; j < 4; ++j)
#pragma unroll
            for (int q = 0; q < 4; ++q) acc[i][j][q] = 0.f;

    // A x4 fragment addressing (validated R2..R8)
    const int arow  = wm * 64 + (lane & 15);
    const int acol8 = (lane >> 4) * 8;
    // B x4 addressing (validated R5): one x4 covers 16 N-rows (two j frags)
    const int brow_l = (lane >> 4) * 8 + (lane & 7);
    const int bk_l   = ((lane >> 3) & 1) * 8;

    const int nch = K / BK;     // >= 8
    prefetch(0, 0); CP_COMMIT();
    prefetch(1, 1); CP_COMMIT();
    prefetch(2, 2); CP_COMMIT();

    for (int c = 0; c < nch; ++c) {
        CP_WAIT2();
        __syncthreads();
        if (c + 3 < nch) prefetch((c + 3) & 3, c + 3);
        CP_COMMIT();

        const uint32_t sb = smem_base + (c & 3) * STAGE_BYTES;
        const uint32_t aB = sb + SM_A, bB = sb + SM_B;

#pragma unroll
        for (int ks = 0; ks < 2; ++ks) {
            uint32_t af[4][4], bf[4][2];
#pragma unroll
            for (int i = 0; i < 4; ++i) {
                uint32_t off = (uint32_t)((arow + i * 16) * SROW + ks * 16 + acol8) * 2;
                ldm_x4(af[i], aB + off);
            }
#pragma unroll
            for (int p = 0; p < 2; ++p) {
                uint32_t off = (uint32_t)((wn * 32 + p * 16 + brow_l) * SROW + ks * 16 + bk_l) * 2;
                ldm_x4(&bf[2 * p][0], bB + off);
            }
#pragma unroll
            for (int i = 0; i < 4; ++i)
#pragma unroll
                for (int j = 0; j < 4; ++j)
                    mma16816(acc[i][j], af[i], bf[j]);
        }
        __syncthreads();
    }

    // ---- epilogue ----
    const int erow0 = wm * 64 + (lane >> 2);
    const int ecol  = wn * 32 + 2 * (lane & 3);

    if (outmode == 0) {
        __half* OhS = Oh + (size_t)a * sOz;
#pragma unroll
        for (int i = 0; i < 4; ++i) {
#pragma unroll
            for (int j = 0; j < 4; ++j) {
                int n_loc = ecol + j * 8;
                float bx = sBias[n_loc], by = sBias[n_loc + 1];
                float vx0 = acc[i][j][0] + bx, vy0 = acc[i][j][1] + by;
                float vx1 = acc[i][j][2] + bx, vy1 = acc[i][j][3] + by;
                if (relu_f) {
                    vx0 = fmaxf(vx0, 0.f); vy0 = fmaxf(vy0, 0.f);
                    vx1 = fmaxf(vx1, 0.f); vy1 = fmaxf(vy1, 0.f);
                }
                size_t p0 = (size_t)(m0 + erow0 + i * 16) * (size_t)ldn + n0 + n_loc;
                size_t p1 = (size_t)(m0 + erow0 + i * 16 + 8) * (size_t)ldn + n0 + n_loc;
                *reinterpret_cast<__half2*>(OhS + p0) = __floats2half2_rn(vx0, vy0);
                *reinterpret_cast<__half2*>(OhS + p1) = __floats2half2_rn(vx1, vy1);
            }
        }
    } else {
        float* Op;
        int ldo;
        if (a < ADIM) { Op = Ofm + (size_t)a * sOfz; ldo = ldo_f; }
        else          { Op = Ofa;                    ldo = ldo_a; }
#pragma unroll
        for (int i = 0; i < 4; ++i) {
#pragma unroll
            for (int j = 0; j < 4; ++j) {
                int n_loc = ecol + j * 8;
                float bx = sBias[n_loc], by = sBias[n_loc + 1];
                float2 v0, v1;
                v0.x = acc[i][j][0] + bx; v0.y = acc[i][j][1] + by;
                v1.x = acc[i][j][2] + bx; v1.y = acc[i][j][3] + by;
                if (relu_f) {
                    v0.x = fmaxf(v0.x, 0.f); v0.y = fmaxf(v0.y, 0.f);
                    v1.x = fmaxf(v1.x, 0.f); v1.y = fmaxf(v1.y, 0.f);
                }
                float* p0 = Op + (size_t)(m0 + erow0 + i * 16) * (size_t)ldo + n0 + n_loc;
                float* p1 = Op + (size_t)(m0 + erow0 + i * 16 + 8) * (size_t)ldo + n0 + n_loc;
                *reinterpret_cast<float2*>(p0) = v0;
                *reinterpret_cast<float2*>(p1) = v1;
            }
        }
    }
}

// ======================================================================
// Combine: psi[b,a,s] = state[b,s] + adv[b,a,s] - mean_a(adv[b,a,s])
// ======================================================================
__global__ void combine_kernel(float* __restrict__ out, const float* __restrict__ state) {
    int idx = blockIdx.x * blockDim.x + threadIdx.x;
    int b = idx >> 6;
    int s4 = (idx & 63) << 2;
    float4* base = reinterpret_cast<float4*>(out + (size_t)b * (ADIM * SF) + s4);
    float4 adv[ADIM];
    float sx = 0.f, sy = 0.f, sz = 0.f, sw = 0.f;
#pragma unroll
    for (int a2 = 0; a2 < ADIM; ++a2) {
        adv[a2] = base[a2 * (SF / 4)];
        sx += adv[a2].x; sy += adv[a2].y; sz += adv[a2].z; sw += adv[a2].w;
    }
    const float inv = 1.0f / ADIM;
    float4 st = *reinterpret_cast<const float4*>(state + (size_t)b * SF + s4);
    float mx = st.x - sx * inv, my = st.y - sy * inv;
    float mz = st.z - sz * inv, mw = st.w - sw * inv;
#pragma unroll
    for (int a2 = 0; a2 < ADIM; ++a2) {
        float4 v;
        v.x = adv[a2].x + mx; v.y = adv[a2].y + my;
        v.z = adv[a2].z + mz; v.w = adv[a2].w + mw;
        base[a2 * (SF / 4)] = v;
    }
}

// ======================================================================
extern "C" void kernel_launch(void* const* d_in, const int* in_sizes, int n_in,
                              void* d_out, int out_size) {
    const float* x  = (const float*)d_in[0];
    const float* W1 = (const float*)d_in[1];
    const float* b1 = (const float*)d_in[2];
    const float* W2 = (const float*)d_in[3];
    const float* b2 = (const float*)d_in[4];
    const float* W3 = (const float*)d_in[5];
    const float* b3 = (const float*)d_in[6];
    const float* V1 = (const float*)d_in[7];
    const float* c1 = (const float*)d_in[8];
    const float* V2 = (const float*)d_in[9];
    const float* c2 = (const float*)d_in[10];
    const float* V3 = (const float*)d_in[11];
    const float* c3 = (const float*)d_in[12];
    float* out = (float*)d_out;

    __half *xh, *H1, *H2, *W1t, *W2t, *W3t;
    float* S;
    cudaGetSymbolAddress((void**)&xh,  g_x);
    cudaGetSymbolAddress((void**)&H1,  g_H1);
    cudaGetSymbolAddress((void**)&H2,  g_H2);
    cudaGetSymbolAddress((void**)&W1t, g_W1);
    cudaGetSymbolAddress((void**)&W2t, g_W2);
    cudaGetSymbolAddress((void**)&W3t, g_W3);
    cudaGetSymbolAddress((void**)&S,   g_S);

    cudaFuncSetAttribute(gemm_mma, cudaFuncAttributeMaxDynamicSharedMemorySize, SMEM_TOTAL);

    // ---- prologue: round x to fp16; transpose+round weights ----
    round_kernel<<<(B_DIM * SF / 4 + 255) / 256, 256>>>(x, xh, B_DIM * SF / 4);
    transpose_round<<<dim3(SF / 32, FC / 32, NSLOT), dim3(32, 8)>>>(
        W1, (size_t)SF * FC, V1, W1t, SF, FC);
    transpose_round<<<dim3(FC / 32, FC / 32, NSLOT), dim3(32, 8)>>>(
        W2, (size_t)FC * FC, V2, W2t, FC, FC);
    transpose_round<<<dim3(FC / 32, SF / 32, NSLOT), dim3(32, 8)>>>(
        W3, (size_t)FC * SF, V3, W3t, FC, SF);

    const size_t sH = (size_t)B_DIM * FC;

    // Layer 1: x[B,256] @ W1^T -> H1 fp16 (A stride 0: all slots read x)
    gemm_mma<<<dim3(B_DIM / BM, FC / BN, NSLOT), NT, SMEM_TOTAL>>>(
        xh, 0,
        W1t, (size_t)FC * SF,
        b1, FC, c1,
        H1, sH,
        nullptr, 0, 0, nullptr, 0,
        SF, FC, 1, 0);

    // Layer 2: H1 @ W2^T -> H2 fp16
    gemm_mma<<<dim3(B_DIM / BM, FC / BN, NSLOT), NT, SMEM_TOTAL>>>(
        H1, sH,
        W2t, (size_t)FC * FC,
        b2, FC, c2,
        H2, sH,
        nullptr, 0, 0, nullptr, 0,
        FC, FC, 1, 0);

    // Layer 3: H2 @ W3^T -> adv (fp32, into out) ; slot 16 -> g_S
    gemm_mma<<<dim3(B_DIM / BM, SF / BN, NSLOT), NT, SMEM_TOTAL>>>(
        H2, sH,
        W3t, (size_t)SF * FC,
        b3, SF, c3,
        nullptr, 0,
        out, SF, ADIM * SF,
        S, SF,
        FC, SF, 0, 1);

    // Combine
    combine_kernel<<<(B_DIM * SF / 4) / 256, 256>>>(out, S);
}